// round 12
// baseline (speedup 1.0000x reference)
#include <cuda_runtime.h>
#include <cuda_bf16.h>
#include <cstdint>

#define EPS 1e-7f
#define BB 16
#define LL 1024
#define DD 256
#define PP 20

#define SW128(o) ((o) ^ (((o) >> 3) & 0x70))

__device__ __forceinline__ uint32_t s2u(const void* p) {
    uint32_t a;
    asm("{ .reg .u64 t; cvta.to.shared.u64 t, %1; cvt.u32.u64 %0, t; }"
        : "=r"(a) : "l"(p));
    return a;
}

__device__ __forceinline__ void ldm_x4(uint32_t* r, uint32_t addr) {
    asm volatile("ldmatrix.sync.aligned.m8n8.x4.shared.b16 {%0,%1,%2,%3}, [%4];"
                 : "=r"(r[0]), "=r"(r[1]), "=r"(r[2]), "=r"(r[3]) : "r"(addr));
}

__device__ __forceinline__ void mma_bf16(float* c, const uint32_t* a, const uint32_t* b) {
    asm volatile(
        "mma.sync.aligned.m16n8k16.row.col.f32.bf16.bf16.f32 "
        "{%0,%1,%2,%3}, {%4,%5,%6,%7}, {%8,%9}, {%0,%1,%2,%3};"
        : "+f"(c[0]), "+f"(c[1]), "+f"(c[2]), "+f"(c[3])
        : "r"(a[0]), "r"(a[1]), "r"(a[2]), "r"(a[3]), "r"(b[0]), "r"(b[1]));
}

__device__ __forceinline__ void cp16(uint32_t dst, const void* src) {
    asm volatile("cp.async.cg.shared.global [%0], [%1], 16;" :: "r"(dst), "l"(src));
}
#define CP_COMMIT asm volatile("cp.async.commit_group;" ::: "memory")
#define CP_WAIT1  asm volatile("cp.async.wait_group 1;" ::: "memory")
#define CP_WAIT0  asm volatile("cp.async.wait_group 0;" ::: "memory")

// ======================= scratch =======================
__device__ float g_vp[BB*DD*32];       // v partials, [(b*DD+d)*32 + mt]
__device__ float g_v[BB*DD];
__device__ float g_Mp[2*BB*DD*DD];     // gram m-split fp32 partials
__device__ __nv_bfloat16 g_zH[BB*DD*LL], g_zL[BB*DD*LL];       // z^T  [b][d][m]
__device__ __nv_bfloat16 g_x1h[BB*LL*DD], g_x1l[BB*LL*DD];     // [b][l][d]
__device__ __nv_bfloat16 g_Mh[BB*DD*DD],  g_Ml[BB*DD*DD];      // [b][i][j]

// ======== K0: s1 — norm + hi/lo split, warp per row ========
__global__ __launch_bounds__(256) void k_prep(const float* __restrict__ s1) {
    int row  = (blockIdx.x * 256 + threadIdx.x) >> 5;   // 0..16383
    int lane = threadIdx.x & 31;
    const float4* p = reinterpret_cast<const float4*>(s1) + (size_t)row * 64;
    float4 a = p[lane * 2], b = p[lane * 2 + 1];
    float ss = a.x*a.x + a.y*a.y + a.z*a.z + a.w*a.w
             + b.x*b.x + b.y*b.y + b.z*b.z + b.w*b.w;
#pragma unroll
    for (int o = 16; o; o >>= 1) ss += __shfl_xor_sync(0xffffffffu, ss, o);
    float inv = rsqrtf(fmaxf(ss, EPS));
    float x[8] = {a.x*inv, a.y*inv, a.z*inv, a.w*inv,
                  b.x*inv, b.y*inv, b.z*inv, b.w*inv};
    __nv_bfloat16 h[8], l[8];
#pragma unroll
    for (int i = 0; i < 8; i++) {
        h[i] = __float2bfloat16(x[i]);
        l[i] = __float2bfloat16(x[i] - __bfloat162float(h[i]));
    }
    int o16 = row * 32 + lane;
    __nv_bfloat162 hh[4] = {{h[0],h[1]},{h[2],h[3]},{h[4],h[5]},{h[6],h[7]}};
    __nv_bfloat162 ll[4] = {{l[0],l[1]},{l[2],l[3]},{l[4],l[5]},{l[6],l[7]}};
    reinterpret_cast<uint4*>(g_x1h)[o16] = *reinterpret_cast<uint4*>(hh);
    reinterpret_cast<uint4*>(g_x1l)[o16] = *reinterpret_cast<uint4*>(ll);
}

// ======== K1: s2 fused — norms + transpose to z^T (hi/lo) + v partials ========
__global__ __launch_bounds__(256) void k_trans(const float* __restrict__ s2) {
    __shared__ float tile[32][257];
    __shared__ float sInvF[32];
    __shared__ float sInvW[32];
    int b = blockIdx.x, mt = blockIdx.y;
    int tid = threadIdx.x, lane = tid & 31, w = tid >> 5;
    const float* src = s2 + ((size_t)(b * LL + mt * 32)) * DD;

#pragma unroll
    for (int r = 0; r < 4; r++) {
        int row = w * 4 + r;
        const float4* p = reinterpret_cast<const float4*>(src + (size_t)row * DD);
        float4 a = p[lane * 2], bb = p[lane * 2 + 1];
        float* t = &tile[row][lane * 8];
        t[0]=a.x; t[1]=a.y; t[2]=a.z; t[3]=a.w;
        t[4]=bb.x; t[5]=bb.y; t[6]=bb.z; t[7]=bb.w;
        float ss = a.x*a.x + a.y*a.y + a.z*a.z + a.w*a.w
                 + bb.x*bb.x + bb.y*bb.y + bb.z*bb.z + bb.w*bb.w;
#pragma unroll
        for (int o = 16; o; o >>= 1) ss += __shfl_xor_sync(0xffffffffu, ss, o);
        if (lane == 0) {
            float inv = rsqrtf(fmaxf(ss, EPS));
            sInvF[row] = inv;
            sInvW[row] = sqrtf(inv);
        }
    }
    __syncthreads();

    {
        float acc = 0.f;
#pragma unroll 8
        for (int m = 0; m < 32; m++) acc += tile[m][tid] * sInvF[m];
        g_vp[((size_t)(b * DD + tid)) * 32 + mt] = acc;
    }

    int p2  = (tid & 15) * 2;
    int dof = tid >> 4;
#pragma unroll
    for (int it = 0; it < 16; it++) {
        int d = it * 16 + dof;
        float v0 = tile[p2][d],     v1 = tile[p2 + 1][d];
        float z0 = v0 * sInvW[p2],  z1 = v1 * sInvW[p2 + 1];
        __nv_bfloat16 h0 = __float2bfloat16(z0);
        __nv_bfloat16 h1 = __float2bfloat16(z1);
        __nv_bfloat16 l0 = __float2bfloat16(z0 - __bfloat162float(h0));
        __nv_bfloat16 l1 = __float2bfloat16(z1 - __bfloat162float(h1));
        size_t o = ((size_t)(b * DD + d)) * LL + mt * 32 + p2;
        *reinterpret_cast<__nv_bfloat162*>(g_zH + o) = {h0, h1};
        *reinterpret_cast<__nv_bfloat162*>(g_zL + o) = {l0, l1};
    }
}

// ============ gram: pipelined CTA tile C[128 x 64], K=512 per m-split ========
#define SM_AH 0
#define SM_AL 16384
#define SM_BH 32768
#define SM_BL 40960
#define BUFSZ 49152

__device__ __forceinline__ void stage_tile(
    uint32_t sb,
    const __nv_bfloat16* __restrict__ aH, const __nv_bfloat16* __restrict__ aL,
    const __nv_bfloat16* __restrict__ bH, const __nv_bfloat16* __restrict__ bL,
    int lda, int ldb, int kc, int tid)
{
#pragma unroll
    for (int q = 0; q < 4; q++) {
        int idx = tid + q * 256;
        int row = idx >> 3, c = idx & 7;
        size_t go = (size_t)row * lda + (size_t)kc * 64 + c * 8;
        uint32_t so = SW128((uint32_t)(row * 128 + c * 16));
        cp16(sb + SM_AH + so, aH + go);
        cp16(sb + SM_AL + so, aL + go);
    }
#pragma unroll
    for (int q = 0; q < 2; q++) {
        int idx = tid + q * 256;
        int row = idx >> 3, c = idx & 7;
        size_t go = (size_t)row * ldb + (size_t)kc * 64 + c * 8;
        uint32_t so = SW128((uint32_t)(row * 128 + c * 16));
        cp16(sb + SM_BH + so, bH + go);
        cp16(sb + SM_BL + so, bL + go);
    }
}

__global__ __launch_bounds__(256) void k_gram_mma() {
    extern __shared__ __align__(128) char sm[];
    uint32_t sb = s2u(sm);
    int b = blockIdx.x, it = blockIdx.y;
    int jt = blockIdx.z & 3, ms = blockIdx.z >> 2;
    const __nv_bfloat16* aH = g_zH + ((size_t)(b * DD + it * 128)) * LL + ms * 512;
    const __nv_bfloat16* aL = g_zL + ((size_t)(b * DD + it * 128)) * LL + ms * 512;
    const __nv_bfloat16* bH = g_zH + ((size_t)(b * DD + jt * 64)) * LL + ms * 512;
    const __nv_bfloat16* bL = g_zL + ((size_t)(b * DD + jt * 64)) * LL + ms * 512;

    int tid = threadIdx.x;
    int lane = tid & 31, wid = tid >> 5;
    int m0 = (wid & 3) * 32;
    int n0 = (wid >> 2) * 32;

    float acc[2][4][4];
#pragma unroll
    for (int mi = 0; mi < 2; mi++)
#pragma unroll
        for (int ni = 0; ni < 4; ni++)
#pragma unroll
            for (int q = 0; q < 4; q++) acc[mi][ni][q] = 0.f;

    uint32_t aoff[2], boff[2];
#pragma unroll
    for (int mi = 0; mi < 2; mi++) {
        int row = m0 + mi*16 + (lane & 15);
        aoff[mi] = SW128((uint32_t)(row * 128 + (lane >> 4) * 16));
    }
#pragma unroll
    for (int np = 0; np < 2; np++) {
        int row = n0 + np*16 + (lane & 7) + ((lane >> 4) << 3);
        boff[np] = SW128((uint32_t)(row * 128 + ((lane >> 3) & 1) * 16));
    }

    stage_tile(sb, aH, aL, bH, bL, LL, LL, 0, tid);
    CP_COMMIT;

    for (int kc = 0; kc < 8; kc++) {
        if (kc + 1 < 8) {
            stage_tile(sb + ((kc + 1) & 1) * BUFSZ, aH, aL, bH, bL, LL, LL, kc + 1, tid);
            CP_COMMIT;
            CP_WAIT1;
        } else {
            CP_WAIT0;
        }
        __syncthreads();

        uint32_t sbuf = sb + (kc & 1) * BUFSZ;
#pragma unroll
        for (int ks = 0; ks < 4; ks++) {
            uint32_t kb = ks * 32;
            uint32_t ah[2][4], al[2][4], bh[2][4], bl[2][4];
#pragma unroll
            for (int mi = 0; mi < 2; mi++) {
                ldm_x4(ah[mi], sbuf + SM_AH + (aoff[mi] ^ kb));
                ldm_x4(al[mi], sbuf + SM_AL + (aoff[mi] ^ kb));
            }
#pragma unroll
            for (int np = 0; np < 2; np++) {
                ldm_x4(bh[np], sbuf + SM_BH + (boff[np] ^ kb));
                ldm_x4(bl[np], sbuf + SM_BL + (boff[np] ^ kb));
            }
#pragma unroll
            for (int mi = 0; mi < 2; mi++)
#pragma unroll
                for (int ni = 0; ni < 4; ni++) {
                    const uint32_t* bph = &bh[ni >> 1][(ni & 1) * 2];
                    const uint32_t* bpl = &bl[ni >> 1][(ni & 1) * 2];
                    mma_bf16(acc[mi][ni], ah[mi], bph);
                    mma_bf16(acc[mi][ni], ah[mi], bpl);
                    mma_bf16(acc[mi][ni], al[mi], bph);
                }
        }
        __syncthreads();
    }

    float* dst = g_Mp + (size_t)ms * BB * DD * DD;
#pragma unroll
    for (int mi = 0; mi < 2; mi++)
#pragma unroll
        for (int ni = 0; ni < 4; ni++) {
            int i = it * 128 + m0 + mi * 16 + (lane >> 2);
            int j = jt * 64 + n0 + ni * 8 + (lane & 3) * 2;
#pragma unroll
            for (int h = 0; h < 2; h++) {
                size_t o = ((size_t)(b * DD + i + h * 8)) * DD + j;
                *reinterpret_cast<float2*>(&dst[o]) =
                    make_float2(acc[mi][ni][h*2], acc[mi][ni][h*2+1]);
            }
        }
}

// ======== K2b: merged — reduce gram partials -> Mh/Ml, and v partials -> g_v
__global__ __launch_bounds__(256) void k_mred() {
    int bid = blockIdx.x;
    if (bid < 1024) {
        int idx = bid * 256 + threadIdx.x;
        const int MF4 = BB * DD * DD / 4;
        const float4* p = reinterpret_cast<const float4*>(g_Mp);
        float4 a = p[idx], b = p[idx + MF4];
        float s[4] = {a.x+b.x, a.y+b.y, a.z+b.z, a.w+b.w};
        __nv_bfloat16 h[4], l[4];
#pragma unroll
        for (int i = 0; i < 4; i++) {
            h[i] = __float2bfloat16(s[i]);
            l[i] = __float2bfloat16(s[i] - __bfloat162float(h[i]));
        }
        reinterpret_cast<__nv_bfloat162*>(g_Mh)[idx*2]   = {h[0], h[1]};
        reinterpret_cast<__nv_bfloat162*>(g_Mh)[idx*2+1] = {h[2], h[3]};
        reinterpret_cast<__nv_bfloat162*>(g_Ml)[idx*2]   = {l[0], l[1]};
        reinterpret_cast<__nv_bfloat162*>(g_Ml)[idx*2+1] = {l[2], l[3]};
    } else {
        int gw   = ((bid - 1024) * 256 + threadIdx.x) >> 5;   // 0..4095
        int lane = threadIdx.x & 31;
        float v = g_vp[(size_t)gw * 32 + lane];
#pragma unroll
        for (int o = 16; o; o >>= 1) v += __shfl_xor_sync(0xffffffffu, v, o);
        if (lane == 0) g_v[gw] = v;
    }
}

// ======== K3: FUSED weighted-GEMM + output epilogue ========
// CTA tile: 64 l-rows x 256 j-cols; grid (b=16, lt=16). W never leaves smem.
#define W_AH 0
#define W_AL 8192
#define W_BH 16384
#define W_BL 49152
#define BUFW 81920
// epilogue smem reuse (post-mainloop):
#define WPAD 260
#define E_W   0                          // W[64][260] fp32 = 66560 B
#define E_KSQ 66560                      // ksq[20*256] fp32 = 20480 B
#define E_V   87040                      // v[256] fp32 = 1024 B
#define E_OB  88064                      // obuf[8][20] fp32 = 640 B

__global__ __launch_bounds__(256) void k_wt_out(const float* __restrict__ ker,
                                                float* __restrict__ out) {
    extern __shared__ __align__(128) char sm[];
    uint32_t sb = s2u(sm);
    float* smf = reinterpret_cast<float*>(sm);
    int b = blockIdx.x, lt = blockIdx.y;
    int l0 = lt * 64;
    int tid = threadIdx.x;
    int lane = tid & 31, wid = tid >> 5;
    int m0 = (wid & 1) * 32;        // 2 m-groups of 32 rows
    int n0 = (wid >> 1) * 64;       // 4 n-groups of 64 cols

    const __nv_bfloat16* aH = g_x1h + ((size_t)(b * LL + l0)) * DD;
    const __nv_bfloat16* aL = g_x1l + ((size_t)(b * LL + l0)) * DD;
    const __nv_bfloat16* bH = g_Mh + (size_t)b * DD * DD;
    const __nv_bfloat16* bL = g_Ml + (size_t)b * DD * DD;

    float acc[2][8][4];
#pragma unroll
    for (int mi = 0; mi < 2; mi++)
#pragma unroll
        for (int ni = 0; ni < 8; ni++)
#pragma unroll
            for (int q = 0; q < 4; q++) acc[mi][ni][q] = 0.f;

    uint32_t aoff[2], boff[4];
#pragma unroll
    for (int mi = 0; mi < 2; mi++) {
        int row = m0 + mi*16 + (lane & 15);
        aoff[mi] = SW128((uint32_t)(row * 128 + (lane >> 4) * 16));
    }
#pragma unroll
    for (int np = 0; np < 4; np++) {
        int row = n0 + np*16 + (lane & 7) + ((lane >> 4) << 3);
        boff[np] = SW128((uint32_t)(row * 128 + ((lane >> 3) & 1) * 16));
    }

    // ---- staging helper (A: 64x64, B: 256x64, hi+lo) ----
    auto stage = [&](uint32_t base, int kc) {
#pragma unroll
        for (int q = 0; q < 2; q++) {
            int idx = tid + q * 256;
            int row = idx >> 3, c = idx & 7;
            size_t go = (size_t)row * DD + (size_t)kc * 64 + c * 8;
            uint32_t so = SW128((uint32_t)(row * 128 + c * 16));
            cp16(base + W_AH + so, aH + go);
            cp16(base + W_AL + so, aL + go);
        }
#pragma unroll
        for (int q = 0; q < 8; q++) {
            int idx = tid + q * 256;
            int row = idx >> 3, c = idx & 7;
            size_t go = (size_t)row * DD + (size_t)kc * 64 + c * 8;
            uint32_t so = SW128((uint32_t)(row * 128 + c * 16));
            cp16(base + W_BH + so, bH + go);
            cp16(base + W_BL + so, bL + go);
        }
    };

    stage(sb, 0);
    CP_COMMIT;

    for (int kc = 0; kc < 4; kc++) {
        if (kc + 1 < 4) {
            stage(sb + ((kc + 1) & 1) * BUFW, kc + 1);
            CP_COMMIT;
            CP_WAIT1;
        } else {
            CP_WAIT0;
        }
        __syncthreads();

        uint32_t sbuf = sb + (kc & 1) * BUFW;
#pragma unroll
        for (int ks = 0; ks < 4; ks++) {
            uint32_t kb = ks * 32;
            uint32_t ah[2][4], al[2][4], bh[4][4], bl[4][4];
#pragma unroll
            for (int mi = 0; mi < 2; mi++) {
                ldm_x4(ah[mi], sbuf + W_AH + (aoff[mi] ^ kb));
                ldm_x4(al[mi], sbuf + W_AL + (aoff[mi] ^ kb));
            }
#pragma unroll
            for (int np = 0; np < 4; np++) {
                ldm_x4(bh[np], sbuf + W_BH + (boff[np] ^ kb));
                ldm_x4(bl[np], sbuf + W_BL + (boff[np] ^ kb));
            }
#pragma unroll
            for (int mi = 0; mi < 2; mi++)
#pragma unroll
                for (int ni = 0; ni < 8; ni++) {
                    const uint32_t* bph = &bh[ni >> 1][(ni & 1) * 2];
                    const uint32_t* bpl = &bl[ni >> 1][(ni & 1) * 2];
                    mma_bf16(acc[mi][ni], ah[mi], bph);
                    mma_bf16(acc[mi][ni], ah[mi], bpl);
                    mma_bf16(acc[mi][ni], al[mi], bph);
                }
        }
        __syncthreads();
    }

    // ---- epilogue: W -> smem, then perspective cosines in place ----
    __syncthreads();
#pragma unroll
    for (int mi = 0; mi < 2; mi++)
#pragma unroll
        for (int ni = 0; ni < 8; ni++) {
            int r = m0 + mi * 16 + (lane >> 2);
            int c = n0 + ni * 8 + (lane & 3) * 2;
#pragma unroll
            for (int h = 0; h < 2; h++)
                *reinterpret_cast<float2*>(&smf[E_W/4 + (r + h*8) * WPAD + c]) =
                    make_float2(acc[mi][ni][h*2], acc[mi][ni][h*2+1]);
        }
    // ksq and v
    for (int i = tid; i < PP * DD; i += 256) {
        float t = ker[i];
        smf[E_KSQ/4 + i] = t * t;
    }
    smf[E_V/4 + tid] = g_v[b * DD + tid];
    __syncthreads();

    // warp per row, 8 rows per warp
    for (int rr = 0; rr < 8; rr++) {
        int row = wid * 8 + rr;              // 0..63 local
        int grow = b * LL + l0 + row;
        uint4 H = reinterpret_cast<const uint4*>(g_x1h)[(size_t)grow * 32 + lane];
        uint4 L = reinterpret_cast<const uint4*>(g_x1l)[(size_t)grow * 32 + lane];
        __nv_bfloat162 hh[4], ll[4];
        *reinterpret_cast<uint4*>(hh) = H;
        *reinterpret_cast<uint4*>(ll) = L;
        float s[8];
#pragma unroll
        for (int q = 0; q < 4; q++) {
            s[q*2]   = __bfloat162float(hh[q].x) + __bfloat162float(ll[q].x);
            s[q*2+1] = __bfloat162float(hh[q].y) + __bfloat162float(ll[q].y);
        }
        float wv[8];
        *reinterpret_cast<float4*>(&wv[0]) = *reinterpret_cast<float4*>(&smf[E_W/4 + row * WPAD + lane * 8]);
        *reinterpret_cast<float4*>(&wv[4]) = *reinterpret_cast<float4*>(&smf[E_W/4 + row * WPAD + lane * 8 + 4]);

        float rs = 0.f;
        const float* vp = &smf[E_V/4 + lane * 8];
#pragma unroll
        for (int i = 0; i < 8; i++) rs += s[i] * vp[i];
#pragma unroll
        for (int o = 16; o; o >>= 1) rs += __shfl_xor_sync(0xffffffffu, rs, o);
        float invd = 1.0f / (rs + EPS);

        float mv[8], smv[8], ssq[8], msq[8];
#pragma unroll
        for (int i = 0; i < 8; i++) {
            mv[i]  = wv[i] * invd;
            smv[i] = s[i] * mv[i];
            ssq[i] = s[i] * s[i];
            msq[i] = mv[i] * mv[i];
        }

        for (int p = 0; p < PP; p++) {
            const float* kp = &smf[E_KSQ/4 + p * DD + lane * 8];
            float4 K0 = *(const float4*)kp;
            float4 K1 = *(const float4*)(kp + 4);
            float kk[8] = {K0.x, K0.y, K0.z, K0.w, K1.x, K1.y, K1.z, K1.w};
            float n = 0.f, d1 = 0.f, d2 = 0.f;
#pragma unroll
            for (int i = 0; i < 8; i++) {
                n  += kk[i] * smv[i];
                d1 += kk[i] * ssq[i];
                d2 += kk[i] * msq[i];
            }
#pragma unroll
            for (int o = 16; o; o >>= 1) {
                n  += __shfl_xor_sync(0xffffffffu, n,  o);
                d1 += __shfl_xor_sync(0xffffffffu, d1, o);
                d2 += __shfl_xor_sync(0xffffffffu, d2, o);
            }
            if (lane == 0)
                smf[E_OB/4 + wid * PP + p] = n * rsqrtf(fmaxf(d1, EPS)) * rsqrtf(fmaxf(d2, EPS));
        }
        __syncwarp();
        if (lane < PP)
            out[(size_t)grow * PP + lane] = smf[E_OB/4 + wid * PP + lane];
        __syncwarp();
    }
}

// ======================= launch =======================
extern "C" void kernel_launch(void* const* d_in, const int* in_sizes, int n_in,
                              void* d_out, int out_size) {
    const float* s1  = (const float*)d_in[0];   // [16,1024,256]
    const float* s2  = (const float*)d_in[1];   // [16,1024,256]
    const float* ker = (const float*)d_in[2];   // [20,256]
    float* out = (float*)d_out;                 // [16,1024,20]

    cudaFuncSetAttribute(k_gram_mma, cudaFuncAttributeMaxDynamicSharedMemorySize, 2*BUFSZ);
    cudaFuncSetAttribute(k_wt_out,   cudaFuncAttributeMaxDynamicSharedMemorySize, 2*BUFW);

    k_prep<<<2048, 256>>>(s1);
    k_trans<<<dim3(16, 32), 256>>>(s2);
    k_gram_mma<<<dim3(16, 2, 8), 256, 2*BUFSZ>>>();
    k_mred<<<1536, 256>>>();
    k_wt_out<<<dim3(16, 16), 256, 2*BUFW>>>(ker, out);
}

// round 15
// speedup vs baseline: 1.2263x; 1.2263x over previous
#include <cuda_runtime.h>
#include <cuda_bf16.h>
#include <cstdint>

#define EPS 1e-7f
#define BB 16
#define LL 1024
#define DD 256
#define PP 20

#define SW128(o) ((o) ^ (((o) >> 3) & 0x70))

__device__ __forceinline__ uint32_t s2u(const void* p) {
    uint32_t a;
    asm("{ .reg .u64 t; cvta.to.shared.u64 t, %1; cvt.u32.u64 %0, t; }"
        : "=r"(a) : "l"(p));
    return a;
}

__device__ __forceinline__ void ldm_x4(uint32_t* r, uint32_t addr) {
    asm volatile("ldmatrix.sync.aligned.m8n8.x4.shared.b16 {%0,%1,%2,%3}, [%4];"
                 : "=r"(r[0]), "=r"(r[1]), "=r"(r[2]), "=r"(r[3]) : "r"(addr));
}

__device__ __forceinline__ void mma_bf16(float* c, const uint32_t* a, const uint32_t* b) {
    asm volatile(
        "mma.sync.aligned.m16n8k16.row.col.f32.bf16.bf16.f32 "
        "{%0,%1,%2,%3}, {%4,%5,%6,%7}, {%8,%9}, {%0,%1,%2,%3};"
        : "+f"(c[0]), "+f"(c[1]), "+f"(c[2]), "+f"(c[3])
        : "r"(a[0]), "r"(a[1]), "r"(a[2]), "r"(a[3]), "r"(b[0]), "r"(b[1]));
}

__device__ __forceinline__ void cp16(uint32_t dst, const void* src) {
    asm volatile("cp.async.cg.shared.global [%0], [%1], 16;" :: "r"(dst), "l"(src));
}
#define CP_COMMIT asm volatile("cp.async.commit_group;" ::: "memory")
#define CP_WAIT1  asm volatile("cp.async.wait_group 1;" ::: "memory")
#define CP_WAIT0  asm volatile("cp.async.wait_group 0;" ::: "memory")

// ======================= scratch =======================
__device__ float g_vp[BB*DD*32];       // v partials, [(b*DD+d)*32 + mt]
__device__ float g_v[BB*DD];
__device__ float g_w[BB*LL*DD];
__device__ __nv_bfloat16 g_zH[BB*DD*LL], g_zL[BB*DD*LL];       // z^T  [b][d][m]
__device__ __nv_bfloat16 g_x1h[BB*LL*DD], g_x1l[BB*LL*DD];     // [b][l][d]
__device__ __nv_bfloat16 g_Mh[BB*DD*DD],  g_Ml[BB*DD*DD];      // [b][i][j]

// ======== K0: MERGED s1-prep + s2-trans (blockIdx branch) ========
// blocks [0,2048): s1 norm + hi/lo split (warp per row)
// blocks [2048,2560): s2 norms + transpose to z^T + v partials
__global__ __launch_bounds__(256) void k_pt(const float* __restrict__ s1,
                                            const float* __restrict__ s2) {
    __shared__ float tile[32][257];
    __shared__ float sInvF[32];
    __shared__ float sInvW[32];
    int bid = blockIdx.x;
    int tid = threadIdx.x, lane = tid & 31, w = tid >> 5;

    if (bid < 2048) {
        // ---- s1 prep ----
        int row = (bid * 256 + tid) >> 5;   // 0..16383
        const float4* p = reinterpret_cast<const float4*>(s1) + (size_t)row * 64;
        float4 a = p[lane * 2], b = p[lane * 2 + 1];
        float ss = a.x*a.x + a.y*a.y + a.z*a.z + a.w*a.w
                 + b.x*b.x + b.y*b.y + b.z*b.z + b.w*b.w;
#pragma unroll
        for (int o = 16; o; o >>= 1) ss += __shfl_xor_sync(0xffffffffu, ss, o);
        float inv = rsqrtf(fmaxf(ss, EPS));
        float x[8] = {a.x*inv, a.y*inv, a.z*inv, a.w*inv,
                      b.x*inv, b.y*inv, b.z*inv, b.w*inv};
        __nv_bfloat16 h[8], l[8];
#pragma unroll
        for (int i = 0; i < 8; i++) {
            h[i] = __float2bfloat16(x[i]);
            l[i] = __float2bfloat16(x[i] - __bfloat162float(h[i]));
        }
        int o16 = row * 32 + lane;
        __nv_bfloat162 hh[4] = {{h[0],h[1]},{h[2],h[3]},{h[4],h[5]},{h[6],h[7]}};
        __nv_bfloat162 ll[4] = {{l[0],l[1]},{l[2],l[3]},{l[4],l[5]},{l[6],l[7]}};
        reinterpret_cast<uint4*>(g_x1h)[o16] = *reinterpret_cast<uint4*>(hh);
        reinterpret_cast<uint4*>(g_x1l)[o16] = *reinterpret_cast<uint4*>(ll);
        return;
    }

    // ---- s2 trans ----
    int r = bid - 2048;                     // 0..511
    int b = r >> 5, mt = r & 31;
    const float* src = s2 + ((size_t)(b * LL + mt * 32)) * DD;

#pragma unroll
    for (int rr = 0; rr < 4; rr++) {
        int row = w * 4 + rr;
        const float4* p = reinterpret_cast<const float4*>(src + (size_t)row * DD);
        float4 a = p[lane * 2], bb = p[lane * 2 + 1];
        float* t = &tile[row][lane * 8];
        t[0]=a.x; t[1]=a.y; t[2]=a.z; t[3]=a.w;
        t[4]=bb.x; t[5]=bb.y; t[6]=bb.z; t[7]=bb.w;
        float ss = a.x*a.x + a.y*a.y + a.z*a.z + a.w*a.w
                 + bb.x*bb.x + bb.y*bb.y + bb.z*bb.z + bb.w*bb.w;
#pragma unroll
        for (int o = 16; o; o >>= 1) ss += __shfl_xor_sync(0xffffffffu, ss, o);
        if (lane == 0) {
            float inv = rsqrtf(fmaxf(ss, EPS));
            sInvF[row] = inv;
            sInvW[row] = sqrtf(inv);
        }
    }
    __syncthreads();

    {
        float acc = 0.f;
#pragma unroll 8
        for (int m = 0; m < 32; m++) acc += tile[m][tid] * sInvF[m];
        g_vp[((size_t)(b * DD + tid)) * 32 + mt] = acc;
    }

    int p2  = (tid & 15) * 2;
    int dof = tid >> 4;
#pragma unroll
    for (int it = 0; it < 16; it++) {
        int d = it * 16 + dof;
        float v0 = tile[p2][d],     v1 = tile[p2 + 1][d];
        float z0 = v0 * sInvW[p2],  z1 = v1 * sInvW[p2 + 1];
        __nv_bfloat16 h0 = __float2bfloat16(z0);
        __nv_bfloat16 h1 = __float2bfloat16(z1);
        __nv_bfloat16 l0 = __float2bfloat16(z0 - __bfloat162float(h0));
        __nv_bfloat16 l1 = __float2bfloat16(z1 - __bfloat162float(h1));
        size_t o = ((size_t)(b * DD + d)) * LL + mt * 32 + p2;
        *reinterpret_cast<__nv_bfloat162*>(g_zH + o) = {h0, h1};
        *reinterpret_cast<__nv_bfloat162*>(g_zL + o) = {l0, l1};
    }
}

// ============ staging for gram (A 128x64, B 64x64, hi+lo) ====================
#define SM_AH 0
#define SM_AL 16384
#define SM_BH 32768
#define SM_BL 40960
#define BUFSZ 49152

__device__ __forceinline__ void stage_tile(
    uint32_t sb,
    const __nv_bfloat16* __restrict__ aH, const __nv_bfloat16* __restrict__ aL,
    const __nv_bfloat16* __restrict__ bH, const __nv_bfloat16* __restrict__ bL,
    int lda, int ldb, int kc, int tid)
{
#pragma unroll
    for (int q = 0; q < 4; q++) {
        int idx = tid + q * 256;
        int row = idx >> 3, c = idx & 7;
        size_t go = (size_t)row * lda + (size_t)kc * 64 + c * 8;
        uint32_t so = SW128((uint32_t)(row * 128 + c * 16));
        cp16(sb + SM_AH + so, aH + go);
        cp16(sb + SM_AL + so, aL + go);
    }
#pragma unroll
    for (int q = 0; q < 2; q++) {
        int idx = tid + q * 256;
        int row = idx >> 3, c = idx & 7;
        size_t go = (size_t)row * ldb + (size_t)kc * 64 + c * 8;
        uint32_t so = SW128((uint32_t)(row * 128 + c * 16));
        cp16(sb + SM_BH + so, bH + go);
        cp16(sb + SM_BL + so, bL + go);
    }
}

// ======== K1: MERGED gram MMA (128 blocks) + v reduce (16 blocks) ========
// gram: M[b][i][j] = sum_m z[m][i]*z[m][j], K=1024, direct bf16 hi/lo out.
__global__ __launch_bounds__(256) void k_gramv() {
    extern __shared__ __align__(128) char sm[];
    int bid = blockIdx.x;
    int tid = threadIdx.x;
    int lane = tid & 31, wid = tid >> 5;

    if (bid >= 128) {
        // ---- v reduce: 16 blocks x 8 warps x 32 outputs each ----
        int base = (bid - 128) * 256 + wid * 32;    // output range start
        for (int q = 0; q < 32; q++) {
            int gw = base + q;
            float v = g_vp[(size_t)gw * 32 + lane];
#pragma unroll
            for (int o = 16; o; o >>= 1) v += __shfl_xor_sync(0xffffffffu, v, o);
            if (lane == 0) g_v[gw] = v;
        }
        return;
    }

    uint32_t sb = s2u(sm);
    int b = bid & 15, it = (bid >> 4) & 1, jt = bid >> 5;
    const __nv_bfloat16* aH = g_zH + ((size_t)(b * DD + it * 128)) * LL;
    const __nv_bfloat16* aL = g_zL + ((size_t)(b * DD + it * 128)) * LL;
    const __nv_bfloat16* bH = g_zH + ((size_t)(b * DD + jt * 64)) * LL;
    const __nv_bfloat16* bL = g_zL + ((size_t)(b * DD + jt * 64)) * LL;

    int m0 = (wid & 3) * 32;
    int n0 = (wid >> 2) * 32;

    float acc[2][4][4];
#pragma unroll
    for (int mi = 0; mi < 2; mi++)
#pragma unroll
        for (int ni = 0; ni < 4; ni++)
#pragma unroll
            for (int q = 0; q < 4; q++) acc[mi][ni][q] = 0.f;

    uint32_t aoff[2], boff[2];
#pragma unroll
    for (int mi = 0; mi < 2; mi++) {
        int row = m0 + mi*16 + (lane & 15);
        aoff[mi] = SW128((uint32_t)(row * 128 + (lane >> 4) * 16));
    }
#pragma unroll
    for (int np = 0; np < 2; np++) {
        int row = n0 + np*16 + (lane & 7) + ((lane >> 4) << 3);
        boff[np] = SW128((uint32_t)(row * 128 + ((lane >> 3) & 1) * 16));
    }

    stage_tile(sb, aH, aL, bH, bL, LL, LL, 0, tid);
    CP_COMMIT;

    for (int kc = 0; kc < 16; kc++) {
        if (kc + 1 < 16) {
            stage_tile(sb + ((kc + 1) & 1) * BUFSZ, aH, aL, bH, bL, LL, LL, kc + 1, tid);
            CP_COMMIT;
            CP_WAIT1;
        } else {
            CP_WAIT0;
        }
        __syncthreads();

        uint32_t sbuf = sb + (kc & 1) * BUFSZ;
#pragma unroll
        for (int ks = 0; ks < 4; ks++) {
            uint32_t kb = ks * 32;
            uint32_t ah[2][4], al[2][4], bh[2][4], bl[2][4];
#pragma unroll
            for (int mi = 0; mi < 2; mi++) {
                ldm_x4(ah[mi], sbuf + SM_AH + (aoff[mi] ^ kb));
                ldm_x4(al[mi], sbuf + SM_AL + (aoff[mi] ^ kb));
            }
#pragma unroll
            for (int np = 0; np < 2; np++) {
                ldm_x4(bh[np], sbuf + SM_BH + (boff[np] ^ kb));
                ldm_x4(bl[np], sbuf + SM_BL + (boff[np] ^ kb));
            }
#pragma unroll
            for (int mi = 0; mi < 2; mi++)
#pragma unroll
                for (int ni = 0; ni < 4; ni++) {
                    const uint32_t* bph = &bh[ni >> 1][(ni & 1) * 2];
                    const uint32_t* bpl = &bl[ni >> 1][(ni & 1) * 2];
                    mma_bf16(acc[mi][ni], ah[mi], bph);
                    mma_bf16(acc[mi][ni], ah[mi], bpl);
                    mma_bf16(acc[mi][ni], al[mi], bph);
                }
        }
        __syncthreads();
    }

    // direct bf16 hi/lo epilogue
#pragma unroll
    for (int mi = 0; mi < 2; mi++)
#pragma unroll
        for (int ni = 0; ni < 4; ni++) {
            int i = it * 128 + m0 + mi * 16 + (lane >> 2);
            int j = jt * 64 + n0 + ni * 8 + (lane & 3) * 2;
#pragma unroll
            for (int h = 0; h < 2; h++) {
                float v0 = acc[mi][ni][h*2], v1 = acc[mi][ni][h*2+1];
                size_t o = ((size_t)(b * DD + i + h * 8)) * DD + j;
                __nv_bfloat16 h0 = __float2bfloat16(v0);
                __nv_bfloat16 h1 = __float2bfloat16(v1);
                *reinterpret_cast<__nv_bfloat162*>(&g_Mh[o]) = {h0, h1};
                *reinterpret_cast<__nv_bfloat162*>(&g_Ml[o]) = {
                    __float2bfloat16(v0 - __bfloat162float(h0)),
                    __float2bfloat16(v1 - __bfloat162float(h1))};
            }
        }
}

// ======== K2: weighted GEMM: W[b][l][j] = sum_k x1[l][k]*M[j][k]; K=256 ====
__global__ __launch_bounds__(256) void k_wt_mma() {
    extern __shared__ __align__(128) char sm[];
    uint32_t sb = s2u(sm);
    int b = blockIdx.x, lt = blockIdx.y, jt = blockIdx.z;
    const __nv_bfloat16* aH = g_x1h + ((size_t)(b * LL + lt * 128)) * DD;
    const __nv_bfloat16* aL = g_x1l + ((size_t)(b * LL + lt * 128)) * DD;
    const __nv_bfloat16* bH = g_Mh + ((size_t)(b * DD + jt * 64)) * DD;
    const __nv_bfloat16* bL = g_Ml + ((size_t)(b * DD + jt * 64)) * DD;

    int tid = threadIdx.x;
    int lane = tid & 31, wid = tid >> 5;
    int m0 = (wid & 3) * 32;
    int n0 = (wid >> 2) * 32;

    float acc[2][4][4];
#pragma unroll
    for (int mi = 0; mi < 2; mi++)
#pragma unroll
        for (int ni = 0; ni < 4; ni++)
#pragma unroll
            for (int q = 0; q < 4; q++) acc[mi][ni][q] = 0.f;

    uint32_t aoff[2], boff[2];
#pragma unroll
    for (int mi = 0; mi < 2; mi++) {
        int row = m0 + mi*16 + (lane & 15);
        aoff[mi] = SW128((uint32_t)(row * 128 + (lane >> 4) * 16));
    }
#pragma unroll
    for (int np = 0; np < 2; np++) {
        int row = n0 + np*16 + (lane & 7) + ((lane >> 4) << 3);
        boff[np] = SW128((uint32_t)(row * 128 + ((lane >> 3) & 1) * 16));
    }

    stage_tile(sb, aH, aL, bH, bL, DD, DD, 0, tid);
    CP_COMMIT;

    for (int kc = 0; kc < 4; kc++) {
        if (kc + 1 < 4) {
            stage_tile(sb + ((kc + 1) & 1) * BUFSZ, aH, aL, bH, bL, DD, DD, kc + 1, tid);
            CP_COMMIT;
            CP_WAIT1;
        } else {
            CP_WAIT0;
        }
        __syncthreads();

        uint32_t sbuf = sb + (kc & 1) * BUFSZ;
#pragma unroll
        for (int ks = 0; ks < 4; ks++) {
            uint32_t kb = ks * 32;
            uint32_t ah[2][4], al[2][4], bh[2][4], bl[2][4];
#pragma unroll
            for (int mi = 0; mi < 2; mi++) {
                ldm_x4(ah[mi], sbuf + SM_AH + (aoff[mi] ^ kb));
                ldm_x4(al[mi], sbuf + SM_AL + (aoff[mi] ^ kb));
            }
#pragma unroll
            for (int np = 0; np < 2; np++) {
                ldm_x4(bh[np], sbuf + SM_BH + (boff[np] ^ kb));
                ldm_x4(bl[np], sbuf + SM_BL + (boff[np] ^ kb));
            }
#pragma unroll
            for (int mi = 0; mi < 2; mi++)
#pragma unroll
                for (int ni = 0; ni < 4; ni++) {
                    const uint32_t* bph = &bh[ni >> 1][(ni & 1) * 2];
                    const uint32_t* bpl = &bl[ni >> 1][(ni & 1) * 2];
                    mma_bf16(acc[mi][ni], ah[mi], bph);
                    mma_bf16(acc[mi][ni], ah[mi], bpl);
                    mma_bf16(acc[mi][ni], al[mi], bph);
                }
        }
        __syncthreads();
    }

#pragma unroll
    for (int mi = 0; mi < 2; mi++)
#pragma unroll
        for (int ni = 0; ni < 4; ni++) {
            int l = lt * 128 + m0 + mi * 16 + (lane >> 2);
            int j = jt * 64 + n0 + ni * 8 + (lane & 3) * 2;
#pragma unroll
            for (int h = 0; h < 2; h++) {
                size_t o = ((size_t)(b * LL + l + h * 8)) * DD + j;
                *reinterpret_cast<float2*>(&g_w[o]) =
                    make_float2(acc[mi][ni][h*2], acc[mi][ni][h*2+1]);
            }
        }
}

// ======================= K3: output epilogue (x1-based) =====================
__global__ __launch_bounds__(256) void k_out(const float* __restrict__ ker,
                                             float* __restrict__ out) {
    __shared__ float ksq[PP * DD];
    __shared__ float vsh[DD];
    __shared__ float obuf[8][PP];
    int tid = threadIdx.x;
    int row0 = blockIdx.x * 8;
    int b = row0 >> 10;
    for (int i = tid; i < PP * DD; i += 256) { float t = ker[i]; ksq[i] = t * t; }
    vsh[tid] = g_v[b * DD + tid];
    __syncthreads();

    int w = tid >> 5, lane = tid & 31;
    int row = row0 + w;

    uint4 H = reinterpret_cast<const uint4*>(g_x1h)[(size_t)row * 32 + lane];
    uint4 L = reinterpret_cast<const uint4*>(g_x1l)[(size_t)row * 32 + lane];
    __nv_bfloat162 hh[4], ll[4];
    *reinterpret_cast<uint4*>(hh) = H;
    *reinterpret_cast<uint4*>(ll) = L;
    float s[8];
#pragma unroll
    for (int q = 0; q < 4; q++) {
        s[q*2]   = __bfloat162float(hh[q].x) + __bfloat162float(ll[q].x);
        s[q*2+1] = __bfloat162float(hh[q].y) + __bfloat162float(ll[q].y);
    }
    const float4* wp = reinterpret_cast<const float4*>(g_w) + (size_t)row * 64;
    float4 W0 = wp[lane * 2], W1 = wp[lane * 2 + 1];
    float wv[8] = {W0.x, W0.y, W0.z, W0.w, W1.x, W1.y, W1.z, W1.w};

    float rs = 0.f;
    const float* vp = &vsh[lane * 8];
#pragma unroll
    for (int i = 0; i < 8; i++) rs += s[i] * vp[i];
#pragma unroll
    for (int o = 16; o; o >>= 1) rs += __shfl_xor_sync(0xffffffffu, rs, o);
    float invd = 1.0f / (rs + EPS);

    float mv[8], sm[8], ssq[8], msq[8];
#pragma unroll
    for (int i = 0; i < 8; i++) {
        mv[i]  = wv[i] * invd;
        sm[i]  = s[i] * mv[i];
        ssq[i] = s[i] * s[i];
        msq[i] = mv[i] * mv[i];
    }

    for (int p = 0; p < PP; p++) {
        const float* kp = &ksq[p * DD + lane * 8];
        float4 K0 = *(const float4*)kp;
        float4 K1 = *(const float4*)(kp + 4);
        float kk[8] = {K0.x, K0.y, K0.z, K0.w, K1.x, K1.y, K1.z, K1.w};
        float n = 0.f, d1 = 0.f, d2 = 0.f;
#pragma unroll
        for (int i = 0; i < 8; i++) {
            n  += kk[i] * sm[i];
            d1 += kk[i] * ssq[i];
            d2 += kk[i] * msq[i];
        }
#pragma unroll
        for (int o = 16; o; o >>= 1) {
            n  += __shfl_xor_sync(0xffffffffu, n,  o);
            d1 += __shfl_xor_sync(0xffffffffu, d1, o);
            d2 += __shfl_xor_sync(0xffffffffu, d2, o);
        }
        if (lane == 0)
            obuf[w][p] = n * rsqrtf(fmaxf(d1, EPS)) * rsqrtf(fmaxf(d2, EPS));
    }
    __syncwarp();
    if (lane < PP) out[(size_t)row * PP + lane] = obuf[w][lane];
}

// ======================= launch =======================
extern "C" void kernel_launch(void* const* d_in, const int* in_sizes, int n_in,
                              void* d_out, int out_size) {
    const float* s1  = (const float*)d_in[0];   // [16,1024,256]
    const float* s2  = (const float*)d_in[1];   // [16,1024,256]
    const float* ker = (const float*)d_in[2];   // [20,256]
    float* out = (float*)d_out;                 // [16,1024,20]

    cudaFuncSetAttribute(k_gramv,  cudaFuncAttributeMaxDynamicSharedMemorySize, 2*BUFSZ);
    cudaFuncSetAttribute(k_wt_mma, cudaFuncAttributeMaxDynamicSharedMemorySize, 2*BUFSZ);

    k_pt<<<2560, 256>>>(s1, s2);
    k_gramv<<<144, 256, 2*BUFSZ>>>();
    k_wt_mma<<<dim3(16, 8, 4), 256, 2*BUFSZ>>>();
    k_out<<<2048, 256>>>(ker, out);
}

// round 16
// speedup vs baseline: 1.4098x; 1.1496x over previous
#include <cuda_runtime.h>
#include <cuda_bf16.h>
#include <cstdint>

#define EPS 1e-7f
#define BB 16
#define LL 1024
#define DD 256
#define PP 20

#define SW128(o) ((o) ^ (((o) >> 3) & 0x70))

__device__ __forceinline__ uint32_t s2u(const void* p) {
    uint32_t a;
    asm("{ .reg .u64 t; cvta.to.shared.u64 t, %1; cvt.u32.u64 %0, t; }"
        : "=r"(a) : "l"(p));
    return a;
}

__device__ __forceinline__ void ldm_x4(uint32_t* r, uint32_t addr) {
    asm volatile("ldmatrix.sync.aligned.m8n8.x4.shared.b16 {%0,%1,%2,%3}, [%4];"
                 : "=r"(r[0]), "=r"(r[1]), "=r"(r[2]), "=r"(r[3]) : "r"(addr));
}

__device__ __forceinline__ void mma_bf16(float* c, const uint32_t* a, const uint32_t* b) {
    asm volatile(
        "mma.sync.aligned.m16n8k16.row.col.f32.bf16.bf16.f32 "
        "{%0,%1,%2,%3}, {%4,%5,%6,%7}, {%8,%9}, {%0,%1,%2,%3};"
        : "+f"(c[0]), "+f"(c[1]), "+f"(c[2]), "+f"(c[3])
        : "r"(a[0]), "r"(a[1]), "r"(a[2]), "r"(a[3]), "r"(b[0]), "r"(b[1]));
}

__device__ __forceinline__ void cp16(uint32_t dst, const void* src) {
    asm volatile("cp.async.cg.shared.global [%0], [%1], 16;" :: "r"(dst), "l"(src));
}
#define CP_COMMIT asm volatile("cp.async.commit_group;" ::: "memory")
#define CP_WAIT1  asm volatile("cp.async.wait_group 1;" ::: "memory")
#define CP_WAIT0  asm volatile("cp.async.wait_group 0;" ::: "memory")

// packed fp32x2 helpers
#define FMA2(acc, a, b) \
    asm("fma.rn.f32x2 %0, %1, %2, %0;" : "+l"(acc) : "l"(a), "l"(b))
__device__ __forceinline__ unsigned long long pack2(float lo, float hi) {
    unsigned long long d;
    asm("mov.b64 %0, {%1, %2};" : "=l"(d) : "r"(__float_as_uint(lo)), "r"(__float_as_uint(hi)));
    return d;
}
__device__ __forceinline__ float lo32(unsigned long long u) { return __uint_as_float((unsigned)u); }
__device__ __forceinline__ float hi32(unsigned long long u) { return __uint_as_float((unsigned)(u >> 32)); }

// ======================= scratch =======================
__device__ float g_vp[BB*DD*32];       // v partials, [(b*DD+d)*32 + mt]
__device__ float g_v[BB*DD];
__device__ float g_w[BB*LL*DD];
__device__ __nv_bfloat16 g_zH[BB*DD*LL], g_zL[BB*DD*LL];       // z^T  [b][d][m]
__device__ __nv_bfloat16 g_x1h[BB*LL*DD], g_x1l[BB*LL*DD];     // [b][l][d]
__device__ __nv_bfloat16 g_Mh[BB*DD*DD],  g_Ml[BB*DD*DD];      // [b][i][j]

// ======== K0: MERGED s1-prep + s2-trans (blockIdx branch) ========
__global__ __launch_bounds__(256) void k_pt(const float* __restrict__ s1,
                                            const float* __restrict__ s2) {
    __shared__ float tile[32][257];
    __shared__ float sInvF[32];
    __shared__ float sInvW[32];
    int bid = blockIdx.x;
    int tid = threadIdx.x, lane = tid & 31, w = tid >> 5;

    if (bid < 2048) {
        int row = (bid * 256 + tid) >> 5;
        const float4* p = reinterpret_cast<const float4*>(s1) + (size_t)row * 64;
        float4 a = p[lane * 2], b = p[lane * 2 + 1];
        float ss = a.x*a.x + a.y*a.y + a.z*a.z + a.w*a.w
                 + b.x*b.x + b.y*b.y + b.z*b.z + b.w*b.w;
#pragma unroll
        for (int o = 16; o; o >>= 1) ss += __shfl_xor_sync(0xffffffffu, ss, o);
        float inv = rsqrtf(fmaxf(ss, EPS));
        float x[8] = {a.x*inv, a.y*inv, a.z*inv, a.w*inv,
                      b.x*inv, b.y*inv, b.z*inv, b.w*inv};
        __nv_bfloat16 h[8], l[8];
#pragma unroll
        for (int i = 0; i < 8; i++) {
            h[i] = __float2bfloat16(x[i]);
            l[i] = __float2bfloat16(x[i] - __bfloat162float(h[i]));
        }
        int o16 = row * 32 + lane;
        __nv_bfloat162 hh[4] = {{h[0],h[1]},{h[2],h[3]},{h[4],h[5]},{h[6],h[7]}};
        __nv_bfloat162 ll[4] = {{l[0],l[1]},{l[2],l[3]},{l[4],l[5]},{l[6],l[7]}};
        reinterpret_cast<uint4*>(g_x1h)[o16] = *reinterpret_cast<uint4*>(hh);
        reinterpret_cast<uint4*>(g_x1l)[o16] = *reinterpret_cast<uint4*>(ll);
        return;
    }

    int r = bid - 2048;
    int b = r >> 5, mt = r & 31;
    const float* src = s2 + ((size_t)(b * LL + mt * 32)) * DD;

#pragma unroll
    for (int rr = 0; rr < 4; rr++) {
        int row = w * 4 + rr;
        const float4* p = reinterpret_cast<const float4*>(src + (size_t)row * DD);
        float4 a = p[lane * 2], bb = p[lane * 2 + 1];
        float* t = &tile[row][lane * 8];
        t[0]=a.x; t[1]=a.y; t[2]=a.z; t[3]=a.w;
        t[4]=bb.x; t[5]=bb.y; t[6]=bb.z; t[7]=bb.w;
        float ss = a.x*a.x + a.y*a.y + a.z*a.z + a.w*a.w
                 + bb.x*bb.x + bb.y*bb.y + bb.z*bb.z + bb.w*bb.w;
#pragma unroll
        for (int o = 16; o; o >>= 1) ss += __shfl_xor_sync(0xffffffffu, ss, o);
        if (lane == 0) {
            float inv = rsqrtf(fmaxf(ss, EPS));
            sInvF[row] = inv;
            sInvW[row] = sqrtf(inv);
        }
    }
    __syncthreads();

    {
        float acc = 0.f;
#pragma unroll 8
        for (int m = 0; m < 32; m++) acc += tile[m][tid] * sInvF[m];
        g_vp[((size_t)(b * DD + tid)) * 32 + mt] = acc;
    }

    int p2  = (tid & 15) * 2;
    int dof = tid >> 4;
#pragma unroll
    for (int it = 0; it < 16; it++) {
        int d = it * 16 + dof;
        float v0 = tile[p2][d],     v1 = tile[p2 + 1][d];
        float z0 = v0 * sInvW[p2],  z1 = v1 * sInvW[p2 + 1];
        __nv_bfloat16 h0 = __float2bfloat16(z0);
        __nv_bfloat16 h1 = __float2bfloat16(z1);
        __nv_bfloat16 l0 = __float2bfloat16(z0 - __bfloat162float(h0));
        __nv_bfloat16 l1 = __float2bfloat16(z1 - __bfloat162float(h1));
        size_t o = ((size_t)(b * DD + d)) * LL + mt * 32 + p2;
        *reinterpret_cast<__nv_bfloat162*>(g_zH + o) = {h0, h1};
        *reinterpret_cast<__nv_bfloat162*>(g_zL + o) = {l0, l1};
    }
}

// ============ staging for GEMMs (A 128x64, B 64x64, hi+lo) ===================
#define SM_AH 0
#define SM_AL 16384
#define SM_BH 32768
#define SM_BL 40960
#define BUFSZ 49152

__device__ __forceinline__ void stage_tile(
    uint32_t sb,
    const __nv_bfloat16* __restrict__ aH, const __nv_bfloat16* __restrict__ aL,
    const __nv_bfloat16* __restrict__ bH, const __nv_bfloat16* __restrict__ bL,
    int lda, int ldb, int kc, int tid)
{
#pragma unroll
    for (int q = 0; q < 4; q++) {
        int idx = tid + q * 256;
        int row = idx >> 3, c = idx & 7;
        size_t go = (size_t)row * lda + (size_t)kc * 64 + c * 8;
        uint32_t so = SW128((uint32_t)(row * 128 + c * 16));
        cp16(sb + SM_AH + so, aH + go);
        cp16(sb + SM_AL + so, aL + go);
    }
#pragma unroll
    for (int q = 0; q < 2; q++) {
        int idx = tid + q * 256;
        int row = idx >> 3, c = idx & 7;
        size_t go = (size_t)row * ldb + (size_t)kc * 64 + c * 8;
        uint32_t so = SW128((uint32_t)(row * 128 + c * 16));
        cp16(sb + SM_BH + so, bH + go);
        cp16(sb + SM_BL + so, bL + go);
    }
}

// ======== K1: MERGED gram MMA (128 blocks) + v reduce (16 blocks) ========
__global__ __launch_bounds__(256) void k_gramv() {
    extern __shared__ __align__(128) char sm[];
    int bid = blockIdx.x;
    int tid = threadIdx.x;
    int lane = tid & 31, wid = tid >> 5;

    if (bid >= 128) {
        int base = (bid - 128) * 256 + wid * 32;
        for (int q = 0; q < 32; q++) {
            int gw = base + q;
            float v = g_vp[(size_t)gw * 32 + lane];
#pragma unroll
            for (int o = 16; o; o >>= 1) v += __shfl_xor_sync(0xffffffffu, v, o);
            if (lane == 0) g_v[gw] = v;
        }
        return;
    }

    uint32_t sb = s2u(sm);
    int b = bid & 15, it = (bid >> 4) & 1, jt = bid >> 5;
    const __nv_bfloat16* aH = g_zH + ((size_t)(b * DD + it * 128)) * LL;
    const __nv_bfloat16* aL = g_zL + ((size_t)(b * DD + it * 128)) * LL;
    const __nv_bfloat16* bH = g_zH + ((size_t)(b * DD + jt * 64)) * LL;
    const __nv_bfloat16* bL = g_zL + ((size_t)(b * DD + jt * 64)) * LL;

    int m0 = (wid & 3) * 32;
    int n0 = (wid >> 2) * 32;

    float acc[2][4][4];
#pragma unroll
    for (int mi = 0; mi < 2; mi++)
#pragma unroll
        for (int ni = 0; ni < 4; ni++)
#pragma unroll
            for (int q = 0; q < 4; q++) acc[mi][ni][q] = 0.f;

    uint32_t aoff[2], boff[2];
#pragma unroll
    for (int mi = 0; mi < 2; mi++) {
        int row = m0 + mi*16 + (lane & 15);
        aoff[mi] = SW128((uint32_t)(row * 128 + (lane >> 4) * 16));
    }
#pragma unroll
    for (int np = 0; np < 2; np++) {
        int row = n0 + np*16 + (lane & 7) + ((lane >> 4) << 3);
        boff[np] = SW128((uint32_t)(row * 128 + ((lane >> 3) & 1) * 16));
    }

    stage_tile(sb, aH, aL, bH, bL, LL, LL, 0, tid);
    CP_COMMIT;

    for (int kc = 0; kc < 16; kc++) {
        if (kc + 1 < 16) {
            stage_tile(sb + ((kc + 1) & 1) * BUFSZ, aH, aL, bH, bL, LL, LL, kc + 1, tid);
            CP_COMMIT;
            CP_WAIT1;
        } else {
            CP_WAIT0;
        }
        __syncthreads();

        uint32_t sbuf = sb + (kc & 1) * BUFSZ;
#pragma unroll
        for (int ks = 0; ks < 4; ks++) {
            uint32_t kb = ks * 32;
            uint32_t ah[2][4], al[2][4], bh[2][4], bl[2][4];
#pragma unroll
            for (int mi = 0; mi < 2; mi++) {
                ldm_x4(ah[mi], sbuf + SM_AH + (aoff[mi] ^ kb));
                ldm_x4(al[mi], sbuf + SM_AL + (aoff[mi] ^ kb));
            }
#pragma unroll
            for (int np = 0; np < 2; np++) {
                ldm_x4(bh[np], sbuf + SM_BH + (boff[np] ^ kb));
                ldm_x4(bl[np], sbuf + SM_BL + (boff[np] ^ kb));
            }
#pragma unroll
            for (int mi = 0; mi < 2; mi++)
#pragma unroll
                for (int ni = 0; ni < 4; ni++) {
                    const uint32_t* bph = &bh[ni >> 1][(ni & 1) * 2];
                    const uint32_t* bpl = &bl[ni >> 1][(ni & 1) * 2];
                    mma_bf16(acc[mi][ni], ah[mi], bph);
                    mma_bf16(acc[mi][ni], ah[mi], bpl);
                    mma_bf16(acc[mi][ni], al[mi], bph);
                }
        }
        __syncthreads();
    }

#pragma unroll
    for (int mi = 0; mi < 2; mi++)
#pragma unroll
        for (int ni = 0; ni < 4; ni++) {
            int i = it * 128 + m0 + mi * 16 + (lane >> 2);
            int j = jt * 64 + n0 + ni * 8 + (lane & 3) * 2;
#pragma unroll
            for (int h = 0; h < 2; h++) {
                float v0 = acc[mi][ni][h*2], v1 = acc[mi][ni][h*2+1];
                size_t o = ((size_t)(b * DD + i + h * 8)) * DD + j;
                __nv_bfloat16 h0 = __float2bfloat16(v0);
                __nv_bfloat16 h1 = __float2bfloat16(v1);
                *reinterpret_cast<__nv_bfloat162*>(&g_Mh[o]) = {h0, h1};
                *reinterpret_cast<__nv_bfloat162*>(&g_Ml[o]) = {
                    __float2bfloat16(v0 - __bfloat162float(h0)),
                    __float2bfloat16(v1 - __bfloat162float(h1))};
            }
        }
}

// ======== K2: weighted GEMM: W[b][l][j] = sum_k x1[l][k]*M[j][k]; K=256 ====
__global__ __launch_bounds__(256) void k_wt_mma() {
    extern __shared__ __align__(128) char sm[];
    uint32_t sb = s2u(sm);
    int b = blockIdx.x, lt = blockIdx.y, jt = blockIdx.z;
    const __nv_bfloat16* aH = g_x1h + ((size_t)(b * LL + lt * 128)) * DD;
    const __nv_bfloat16* aL = g_x1l + ((size_t)(b * LL + lt * 128)) * DD;
    const __nv_bfloat16* bH = g_Mh + ((size_t)(b * DD + jt * 64)) * DD;
    const __nv_bfloat16* bL = g_Ml + ((size_t)(b * DD + jt * 64)) * DD;

    int tid = threadIdx.x;
    int lane = tid & 31, wid = tid >> 5;
    int m0 = (wid & 3) * 32;
    int n0 = (wid >> 2) * 32;

    float acc[2][4][4];
#pragma unroll
    for (int mi = 0; mi < 2; mi++)
#pragma unroll
        for (int ni = 0; ni < 4; ni++)
#pragma unroll
            for (int q = 0; q < 4; q++) acc[mi][ni][q] = 0.f;

    uint32_t aoff[2], boff[2];
#pragma unroll
    for (int mi = 0; mi < 2; mi++) {
        int row = m0 + mi*16 + (lane & 15);
        aoff[mi] = SW128((uint32_t)(row * 128 + (lane >> 4) * 16));
    }
#pragma unroll
    for (int np = 0; np < 2; np++) {
        int row = n0 + np*16 + (lane & 7) + ((lane >> 4) << 3);
        boff[np] = SW128((uint32_t)(row * 128 + ((lane >> 3) & 1) * 16));
    }

    stage_tile(sb, aH, aL, bH, bL, DD, DD, 0, tid);
    CP_COMMIT;

    for (int kc = 0; kc < 4; kc++) {
        if (kc + 1 < 4) {
            stage_tile(sb + ((kc + 1) & 1) * BUFSZ, aH, aL, bH, bL, DD, DD, kc + 1, tid);
            CP_COMMIT;
            CP_WAIT1;
        } else {
            CP_WAIT0;
        }
        __syncthreads();

        uint32_t sbuf = sb + (kc & 1) * BUFSZ;
#pragma unroll
        for (int ks = 0; ks < 4; ks++) {
            uint32_t kb = ks * 32;
            uint32_t ah[2][4], al[2][4], bh[2][4], bl[2][4];
#pragma unroll
            for (int mi = 0; mi < 2; mi++) {
                ldm_x4(ah[mi], sbuf + SM_AH + (aoff[mi] ^ kb));
                ldm_x4(al[mi], sbuf + SM_AL + (aoff[mi] ^ kb));
            }
#pragma unroll
            for (int np = 0; np < 2; np++) {
                ldm_x4(bh[np], sbuf + SM_BH + (boff[np] ^ kb));
                ldm_x4(bl[np], sbuf + SM_BL + (boff[np] ^ kb));
            }
#pragma unroll
            for (int mi = 0; mi < 2; mi++)
#pragma unroll
                for (int ni = 0; ni < 4; ni++) {
                    const uint32_t* bph = &bh[ni >> 1][(ni & 1) * 2];
                    const uint32_t* bpl = &bl[ni >> 1][(ni & 1) * 2];
                    mma_bf16(acc[mi][ni], ah[mi], bph);
                    mma_bf16(acc[mi][ni], ah[mi], bpl);
                    mma_bf16(acc[mi][ni], al[mi], bph);
                }
        }
        __syncthreads();
    }

#pragma unroll
    for (int mi = 0; mi < 2; mi++)
#pragma unroll
        for (int ni = 0; ni < 4; ni++) {
            int l = lt * 128 + m0 + mi * 16 + (lane >> 2);
            int j = jt * 64 + n0 + ni * 8 + (lane & 3) * 2;
#pragma unroll
            for (int h = 0; h < 2; h++) {
                size_t o = ((size_t)(b * LL + l + h * 8)) * DD + j;
                *reinterpret_cast<float2*>(&g_w[o]) =
                    make_float2(acc[mi][ni][h*2], acc[mi][ni][h*2+1]);
            }
        }
}

// ======================= K3: output epilogue v2 =============================
// 8-lane groups: warp = 4 rows, lane covers 32 contiguous d. Block = 32 rows.
// ksq seg-padded [20][8][36]; kk LDS broadcast across groups; FMA2 p-loop.
__global__ __launch_bounds__(256) void k_out(const float* __restrict__ ker,
                                             float* __restrict__ out) {
    __shared__ float ksq[PP * 288];     // [p][seg][36]
    __shared__ float vsm[8 * 36];       // [seg][36]
    int tid = threadIdx.x;
    int wid = tid >> 5, lane = tid & 31;
    int g = lane >> 3, sub = lane & 7;
    int row0 = blockIdx.x * 32;
    int b = blockIdx.x >> 5;
    int row = row0 + wid * 4 + g;

    for (int i = tid; i < PP * DD; i += 256) {
        int p = i >> 8, d = i & 255;
        float t = ker[i];
        ksq[p * 288 + (d >> 5) * 36 + (d & 31)] = t * t;
    }
    vsm[(tid >> 5) * 36 + (tid & 31)] = g_v[b * DD + tid];
    __syncthreads();

    // ---- prologue: build packed u=s*wv, q=s*s, w=wv*wv pairs; rs partial ----
    unsigned long long u2[16], q2[16], w2[16];
    float rsp = 0.f;
    const uint4*  xh = reinterpret_cast<const uint4*>(g_x1h + (size_t)row * DD + sub * 32);
    const uint4*  xl = reinterpret_cast<const uint4*>(g_x1l + (size_t)row * DD + sub * 32);
    const float4* wp = reinterpret_cast<const float4*>(g_w + (size_t)row * DD + sub * 32);
    const float*  vp = &vsm[sub * 36];

#pragma unroll
    for (int c = 0; c < 4; c++) {           // chunks of 8 d
        uint4 H = xh[c], L = xl[c];
        float s[8];
        uint32_t hu[4] = {H.x, H.y, H.z, H.w};
        uint32_t lu[4] = {L.x, L.y, L.z, L.w};
#pragma unroll
        for (int k = 0; k < 4; k++) {
            s[2*k]   = __uint_as_float(hu[k] << 16) + __uint_as_float(lu[k] << 16);
            s[2*k+1] = __uint_as_float(hu[k] & 0xFFFF0000u) + __uint_as_float(lu[k] & 0xFFFF0000u);
        }
        float4 Wa = wp[c*2], Wb = wp[c*2+1];
        float wv[8] = {Wa.x, Wa.y, Wa.z, Wa.w, Wb.x, Wb.y, Wb.z, Wb.w};
#pragma unroll
        for (int k = 0; k < 8; k++) rsp += s[k] * vp[c*8 + k];
#pragma unroll
        for (int k = 0; k < 4; k++) {
            u2[c*4+k] = pack2(s[2*k]*wv[2*k],   s[2*k+1]*wv[2*k+1]);
            q2[c*4+k] = pack2(s[2*k]*s[2*k],    s[2*k+1]*s[2*k+1]);
            w2[c*4+k] = pack2(wv[2*k]*wv[2*k],  wv[2*k+1]*wv[2*k+1]);
        }
    }
    // rs: 3-stage butterfly within 8-lane group
#pragma unroll
    for (int o = 4; o; o >>= 1) rsp += __shfl_xor_sync(0xffffffffu, rsp, o);
    float invd = 1.0f / (rsp + EPS);
    float invd2 = invd * invd;

    // ---- p-loop ----
    float o0 = 0.f, o1 = 0.f, o2v = 0.f;
#pragma unroll 4
    for (int p = 0; p < PP; p++) {
        unsigned long long a1 = 0ull, a2 = 0ull, a3 = 0ull;
        const unsigned long long* kp =
            reinterpret_cast<const unsigned long long*>(&ksq[p * 288 + sub * 36]);
#pragma unroll
        for (int j = 0; j < 8; j++) {
            unsigned long long k0 = kp[j*2], k1 = kp[j*2+1];   // LDS.128 pair
            FMA2(a1, k0, u2[j*2]); FMA2(a1, k1, u2[j*2+1]);
            FMA2(a2, k0, q2[j*2]); FMA2(a2, k1, q2[j*2+1]);
            FMA2(a3, k0, w2[j*2]); FMA2(a3, k1, w2[j*2+1]);
        }
        float G1 = lo32(a1) + hi32(a1);
        float G2 = lo32(a2) + hi32(a2);
        float G3 = lo32(a3) + hi32(a3);
#pragma unroll
        for (int o = 4; o; o >>= 1) {
            G1 += __shfl_xor_sync(0xffffffffu, G1, o);
            G2 += __shfl_xor_sync(0xffffffffu, G2, o);
            G3 += __shfl_xor_sync(0xffffffffu, G3, o);
        }
        float val = (G1 * invd) * rsqrtf(fmaxf(G2, EPS))
                                * rsqrtf(fmaxf(G3 * invd2, EPS));
        if ((p & 7) == sub) {
            if (p < 8) o0 = val; else if (p < 16) o1 = val; else o2v = val;
        }
    }

    float* orow = out + (size_t)row * PP;
    orow[sub] = o0;
    orow[sub + 8] = o1;
    if (sub < 4) orow[sub + 16] = o2v;
}

// ======================= launch =======================
extern "C" void kernel_launch(void* const* d_in, const int* in_sizes, int n_in,
                              void* d_out, int out_size) {
    const float* s1  = (const float*)d_in[0];   // [16,1024,256]
    const float* s2  = (const float*)d_in[1];   // [16,1024,256]
    const float* ker = (const float*)d_in[2];   // [20,256]
    float* out = (float*)d_out;                 // [16,1024,20]

    cudaFuncSetAttribute(k_gramv,  cudaFuncAttributeMaxDynamicSharedMemorySize, 2*BUFSZ);
    cudaFuncSetAttribute(k_wt_mma, cudaFuncAttributeMaxDynamicSharedMemorySize, 2*BUFSZ);

    k_pt<<<2560, 256>>>(s1, s2);
    k_gramv<<<144, 256, 2*BUFSZ>>>();
    k_wt_mma<<<dim3(16, 8, 4), 256, 2*BUFSZ>>>();
    k_out<<<512, 256>>>(ker, out);
}